// round 1
// baseline (speedup 1.0000x reference)
#include <cuda_runtime.h>
#include <math.h>

#define VOCAB   50257
#define DIM     512
#define MAXDEP  20
#define NTOK    8192   // B*S = 8*1024

// Scratch for per-token NLL (allocation-free per harness rules).
__device__ float g_tok_nll[NTOK];

// One warp per token. 256 threads = 8 warps per block, 1024 blocks.
__global__ void __launch_bounds__(256) hs_token_kernel(
    const float* __restrict__ hidden,      // [NTOK, DIM]
    const float* __restrict__ node_emb,    // [VOCAB-1, DIM]
    const float* __restrict__ path_signs,  // [VOCAB, MAXDEP]
    const int*   __restrict__ targets,     // [NTOK]
    const int*   __restrict__ path_nodes,  // [VOCAB, MAXDEP]
    const int*   __restrict__ path_lens)   // [VOCAB]
{
    const int gwarp = (blockIdx.x * blockDim.x + threadIdx.x) >> 5;
    const int lane  = threadIdx.x & 31;
    if (gwarp >= NTOK) return;

    const int t   = targets[gwarp];
    int       len = path_lens[t];
    if (len < 1) len = 1;

    // Load this token's hidden row into registers: 16 floats/lane, coalesced.
    const float4* h4 = reinterpret_cast<const float4*>(hidden + (size_t)gwarp * DIM);
    const float4 h0 = h4[lane];
    const float4 h1 = h4[lane + 32];
    const float4 h2 = h4[lane + 64];
    const float4 h3 = h4[lane + 96];

    const int*   nodes = path_nodes + (size_t)t * MAXDEP;
    const float* signs = path_signs + (size_t)t * MAXDEP;

    float nll = 0.0f;

    for (int d = 0; d < len; ++d) {
        const int node = nodes[d];   // broadcast load (all lanes same addr)
        const float4* w4 = reinterpret_cast<const float4*>(node_emb + (size_t)node * DIM);
        const float4 w0 = w4[lane];
        const float4 w1 = w4[lane + 32];
        const float4 w2 = w4[lane + 64];
        const float4 w3 = w4[lane + 96];

        float acc;
        acc  = h0.x * w0.x; acc = fmaf(h0.y, w0.y, acc);
        acc  = fmaf(h0.z, w0.z, acc); acc = fmaf(h0.w, w0.w, acc);
        acc  = fmaf(h1.x, w1.x, acc); acc = fmaf(h1.y, w1.y, acc);
        acc  = fmaf(h1.z, w1.z, acc); acc = fmaf(h1.w, w1.w, acc);
        acc  = fmaf(h2.x, w2.x, acc); acc = fmaf(h2.y, w2.y, acc);
        acc  = fmaf(h2.z, w2.z, acc); acc = fmaf(h2.w, w2.w, acc);
        acc  = fmaf(h3.x, w3.x, acc); acc = fmaf(h3.y, w3.y, acc);
        acc  = fmaf(h3.z, w3.z, acc); acc = fmaf(h3.w, w3.w, acc);

        // Warp reduction -> every lane holds the full dot product.
        #pragma unroll
        for (int off = 16; off > 0; off >>= 1)
            acc += __shfl_xor_sync(0xffffffffu, acc, off);

        const float s = (signs[d] >= 0.0f) ? 1.0f : -1.0f;
        const float z = s * acc;
        // -log sigmoid(z) = max(-z, 0) + log1p(exp(-|z|))   (stable)
        nll += fmaxf(-z, 0.0f) + log1pf(expf(-fabsf(z)));
    }

    if (lane == 0) g_tok_nll[gwarp] = nll;
}

// Deterministic single-block reduction to the scalar mean.
__global__ void __launch_bounds__(1024) hs_reduce_kernel(float* __restrict__ out)
{
    __shared__ float sm[1024];
    const int tid = threadIdx.x;
    float s = 0.0f;
    #pragma unroll
    for (int i = tid; i < NTOK; i += 1024) s += g_tok_nll[i];
    sm[tid] = s;
    __syncthreads();
    #pragma unroll
    for (int k = 512; k > 0; k >>= 1) {
        if (tid < k) sm[tid] += sm[tid + k];
        __syncthreads();
    }
    if (tid == 0) out[0] = sm[0] * (1.0f / (float)NTOK);
}

extern "C" void kernel_launch(void* const* d_in, const int* in_sizes, int n_in,
                              void* d_out, int out_size)
{
    const float* hidden     = (const float*)d_in[0];
    const float* node_emb   = (const float*)d_in[1];
    const float* path_signs = (const float*)d_in[2];
    const int*   targets    = (const int*)  d_in[3];
    const int*   path_nodes = (const int*)  d_in[4];
    const int*   path_lens  = (const int*)  d_in[5];
    float*       out        = (float*)d_out;

    // 8 warps (tokens) per 256-thread block -> 1024 blocks cover 8192 tokens.
    hs_token_kernel<<<NTOK / 8, 256>>>(hidden, node_emb, path_signs,
                                       targets, path_nodes, path_lens);
    hs_reduce_kernel<<<1, 1024>>>(out);
}